// round 14
// baseline (speedup 1.0000x reference)
#include <cuda_runtime.h>
#include <cuda_bf16.h>
#include <cuda_fp16.h>
#include <math.h>
#include <stdint.h>

// OneClassLoss on GB300 — R7.
//  legacy: fft_row (512 blk, half2 spec + norms) -> fft_col (256 blk, psd
//          accumulated over 8 pairs/block -> 16 partials) -> psd_red (128 blk,
//          Hermitian pair log-reduce -> 128 scalars)
//  s1:     gram_fused (128 blk, K=128, bf16 hi/lo HMMA) -> dist_partial ->
//          [ev_row] dist_final
//  join:   final (CE + psd scalar sums)

#define NPIX 16384

__device__ __half2 g_spec[128 * NPIX];      // row-FFT out, [pair][col][row] (8 MB)
__device__ float  g_psd_part[16 * NPIX];    // psd partials per pair-group (1 MB)
__device__ float  g_gram_part[128 * NPIX];  // partial Gram per K-chunk (8 MB)
__device__ float  g_dtmp[8 * NPIX];
__device__ float  g_np1[512], g_np2[512];   // norm partials (4 per image)
__device__ float  g_dist[NPIX];
__device__ float  g_redL[128], g_redA[128]; // per-col psd partial sums

// ---------------------------------------------------------------------------
// 128-pt DIF radix-2 complex FFT, one warp, 4 values/lane (n = r*32+lane).
// Output slot p holds bin rev7(p).
// ---------------------------------------------------------------------------
__device__ __forceinline__ void fft128(float vr[4], float vi[4],
                                       const float2* __restrict__ tw, int lane) {
    #pragma unroll
    for (int r = 0; r < 2; r++) {  // h=64
        float2 w = tw[r * 32 + lane];
        float ur = vr[r], ui = vi[r], xr = vr[r + 2], xi = vi[r + 2];
        vr[r] = ur + xr; vi[r] = ui + xi;
        float dr = ur - xr, di = ui - xi;
        vr[r + 2] = dr * w.x - di * w.y;
        vi[r + 2] = dr * w.y + di * w.x;
    }
    {  // h=32
        float2 w = tw[2 * lane];
        #pragma unroll
        for (int half = 0; half < 2; half++) {
            int r = half * 2;
            float ur = vr[r], ui = vi[r], xr = vr[r + 1], xi = vi[r + 1];
            vr[r] = ur + xr; vi[r] = ui + xi;
            float dr = ur - xr, di = ui - xi;
            vr[r + 1] = dr * w.x - di * w.y;
            vi[r + 1] = dr * w.y + di * w.x;
        }
    }
    #pragma unroll
    for (int st = 0; st < 5; st++) {  // h = 16,8,4,2,1
        const int h = 16 >> st;
        const int k = (lane & (h - 1)) * (64 / h);
        float2 w = tw[k];
        bool hiLane = (lane & h) != 0;
        #pragma unroll
        for (int r = 0; r < 4; r++) {
            float ar = vr[r], ai = vi[r];
            float br = __shfl_xor_sync(0xffffffffu, ar, h);
            float bi = __shfl_xor_sync(0xffffffffu, ai, h);
            if (hiLane) {
                float dr = br - ar, di = bi - ai;
                vr[r] = dr * w.x - di * w.y;
                vi[r] = dr * w.y + di * w.x;
            } else {
                vr[r] = ar + br;
                vi[r] = ai + bi;
            }
        }
    }
}

__device__ __forceinline__ void init_tw(float2* s_tw, int t) {
    if (t < 64) {
        float sn, cs;
        sincosf(-6.283185307179586f * (float)t / 128.0f, &sn, &cs);
        s_tw[t] = make_float2(cs, sn);
    }
}

// ---------------------------------------------------------------------------
// fft_row: grid 512 = 128 pairs x 4 row-groups of 32. z = x1 + i*x2.
// De-bitrev + transpose in smem; write half2 g_spec[pair][col][rows]. Norms.
// ---------------------------------------------------------------------------
__global__ __launch_bounds__(256)
void fft_row_kernel(const float* __restrict__ x1, const float* __restrict__ x2) {
    __shared__ float s_re[128 * 33], s_im[128 * 33];
    __shared__ float2 s_tw[64];
    __shared__ float s_red[16];

    int t = threadIdx.x, lane = t & 31, warp = t >> 5;  // 8 warps
    int b = blockIdx.x >> 2, rg = blockIdx.x & 3;
    const float* p1 = x1 + (size_t)b * NPIX;
    const float* p2 = x2 + (size_t)b * NPIX;

    init_tw(s_tw, t);
    __syncthreads();

    float n1 = 0.f, n2 = 0.f;
    #pragma unroll
    for (int q = 0; q < 4; q++) {
        int rl = warp * 4 + q;
        int row = rg * 32 + rl;
        float vr[4], vi[4];
        #pragma unroll
        for (int r = 0; r < 4; r++) {
            float xr = p1[row * 128 + r * 32 + lane];
            float xi = p2[row * 128 + r * 32 + lane];
            vr[r] = xr; vi[r] = xi;
            n1 += xr * xr; n2 += xi * xi;
        }
        fft128(vr, vi, s_tw, lane);
        #pragma unroll
        for (int r = 0; r < 4; r++) {
            int p = r * 32 + lane;
            int k = __brev((unsigned)p) >> 25;  // natural col bin
            s_re[k * 33 + rl] = vr[r];
            s_im[k * 33 + rl] = vi[r];
        }
    }

    #pragma unroll
    for (int o = 16; o; o >>= 1) {
        n1 += __shfl_xor_sync(0xffffffffu, n1, o);
        n2 += __shfl_xor_sync(0xffffffffu, n2, o);
    }
    if (lane == 0) { s_red[warp] = n1; s_red[8 + warp] = n2; }
    __syncthreads();
    if (t == 0) {
        float a = 0.f, c = 0.f;
        #pragma unroll
        for (int w = 0; w < 8; w++) { a += s_red[w]; c += s_red[8 + w]; }
        g_np1[blockIdx.x] = a; g_np2[blockIdx.x] = c;
    }

    __half2* spec = g_spec + (size_t)b * NPIX;
    #pragma unroll
    for (int it = 0; it < 16; it++) {
        int c = warp + it * 8;
        spec[c * 128 + rg * 32 + lane] =
            __floats2half2_rn(s_re[c * 33 + lane], s_im[c * 33 + lane]);
    }
}

// ---------------------------------------------------------------------------
// fft_col: grid 256 = 16 pair-groups x 16 col-groups. Warp w handles col
// cg*8+w, loops 8 pairs, accumulates |Z|^2 in regs -> g_psd_part[pg].
// ---------------------------------------------------------------------------
__global__ __launch_bounds__(256)
void fft_col_kernel() {
    __shared__ float2 s_tw[64];
    int t = threadIdx.x, lane = t & 31, warp = t >> 5;
    int pg = blockIdx.x >> 4, cg = blockIdx.x & 15;
    int col = cg * 8 + warp;
    init_tw(s_tw, t);
    __syncthreads();

    float acc[4] = {0.f, 0.f, 0.f, 0.f};
    #pragma unroll 2
    for (int q = 0; q < 8; q++) {
        int b = pg * 8 + q;
        const __half2* spec = g_spec + (size_t)b * NPIX + col * 128;
        float vr[4], vi[4];
        #pragma unroll
        for (int r = 0; r < 4; r++) {
            float2 z = __half22float2(spec[r * 32 + lane]);
            vr[r] = z.x; vi[r] = z.y;
        }
        fft128(vr, vi, s_tw, lane);
        #pragma unroll
        for (int r = 0; r < 4; r++)
            acc[r] += vr[r] * vr[r] + vi[r] * vi[r];
    }
    float* outp = g_psd_part + (size_t)pg * NPIX + col * 128;
    #pragma unroll
    for (int r = 0; r < 4; r++) outp[r * 32 + lane] = acc[r];
}

// ---------------------------------------------------------------------------
// psd_red: grid 128 (one block per col). Per slot: sum 16 partials for slot
// AND Hermitian partner, avg = (S_i + S_ip) * 0.5/256; block-reduce
// log(avg) and avg -> g_redL/g_redA[col]. (1 MB + partner reads, L2-hot.)
// ---------------------------------------------------------------------------
__global__ __launch_bounds__(128)
void psd_red_kernel() {
    __shared__ float sbuf[8];
    int t = threadIdx.x, lane = t & 31, warp = t >> 5;
    int col = blockIdx.x, p = t;
    int i = col * 128 + p;
    int kr = __brev((unsigned)p) >> 25;
    int pp = __brev((unsigned)((128 - kr) & 127)) >> 25;
    int ip = ((128 - col) & 127) * 128 + pp;
    float Ti = 0.f, Tp = 0.f;
    #pragma unroll
    for (int y = 0; y < 16; y++) {
        Ti += g_psd_part[(size_t)y * NPIX + i];
        Tp += g_psd_part[(size_t)y * NPIX + ip];
    }
    float avg = (Ti + Tp) * (0.5f / 256.f);
    float v1 = logf(avg), v2 = avg;
    #pragma unroll
    for (int o = 16; o; o >>= 1) {
        v1 += __shfl_xor_sync(0xffffffffu, v1, o);
        v2 += __shfl_xor_sync(0xffffffffu, v2, o);
    }
    if (lane == 0) { sbuf[warp] = v1; sbuf[4 + warp] = v2; }
    __syncthreads();
    if (t == 0) {
        g_redL[col] = sbuf[0] + sbuf[1] + sbuf[2] + sbuf[3];
        g_redA[col] = sbuf[4] + sbuf[5] + sbuf[6] + sbuf[7];
    }
}

// ---------------------------------------------------------------------------
// gram_fused: 128 blocks, K-chunk 128 (2 stages of 64). fp32 load -> bf16
// hi/lo split in smem -> Ahi*Bhi + Ahi*Blo + Alo*Bhi HMMA accumulation.
// ---------------------------------------------------------------------------
__device__ __forceinline__ void ldsm4(uint32_t& r0, uint32_t& r1,
                                      uint32_t& r2, uint32_t& r3, uint32_t a) {
    asm volatile("ldmatrix.sync.aligned.m8n8.x4.shared.b16 {%0,%1,%2,%3}, [%4];"
                 : "=r"(r0), "=r"(r1), "=r"(r2), "=r"(r3) : "r"(a));
}
__device__ __forceinline__ void mma16816(float d[4], const uint32_t a[4],
                                         uint32_t b0, uint32_t b1) {
    asm volatile(
        "mma.sync.aligned.m16n8k16.row.col.f32.bf16.bf16.f32 "
        "{%0,%1,%2,%3}, {%4,%5,%6,%7}, {%8,%9}, {%0,%1,%2,%3};"
        : "+f"(d[0]), "+f"(d[1]), "+f"(d[2]), "+f"(d[3])
        : "r"(a[0]), "r"(a[1]), "r"(a[2]), "r"(a[3]), "r"(b0), "r"(b1));
}

#define SR 144  // smem row stride bytes (64 bf16 + pad)

__global__ __launch_bounds__(256, 2)
void gram_fused_kernel(const float* __restrict__ x1, const float* __restrict__ x2) {
    extern __shared__ char gsm[];
    char* sAhi = gsm;
    char* sAlo = gsm + 128 * SR;
    char* sBhi = gsm + 2 * 128 * SR;
    char* sBlo = gsm + 3 * 128 * SR;
    uint32_t uAhi = (uint32_t)__cvta_generic_to_shared(sAhi);
    uint32_t uAlo = (uint32_t)__cvta_generic_to_shared(sAlo);
    uint32_t uBhi = (uint32_t)__cvta_generic_to_shared(sBhi);
    uint32_t uBlo = (uint32_t)__cvta_generic_to_shared(sBlo);

    int t = threadIdx.x, lane = t & 31, ws = t >> 5;
    int k0 = blockIdx.x * 128;

    float acc[16][4];
    #pragma unroll
    for (int i = 0; i < 16; i++)
        #pragma unroll
        for (int j = 0; j < 4; j++) acc[i][j] = 0.f;

    uint32_t aOff = (ws * 16 + (lane & 15)) * SR + (lane >> 4) * 16;
    uint32_t bOff = ((lane & 7) + ((lane >> 4) << 3)) * SR + ((lane & 8) << 1);

    for (int stg = 0; stg < 2; stg++) {
        int ks = k0 + stg * 64;
        __syncthreads();
        #pragma unroll
        for (int c = 0; c < 8; c++) {
            int id = t + c * 256;
            int row = id >> 4, o = id & 15;
            float4 va = *(const float4*)(x1 + (size_t)row * NPIX + ks + o * 4);
            float4 vb = *(const float4*)(x2 + (size_t)row * NPIX + ks + o * 4);
            __nv_bfloat16 h0 = __float2bfloat16_rn(va.x), h1 = __float2bfloat16_rn(va.y);
            __nv_bfloat16 h2 = __float2bfloat16_rn(va.z), h3 = __float2bfloat16_rn(va.w);
            __nv_bfloat162 ahi0(h0, h1), ahi1(h2, h3);
            __nv_bfloat162 alo0(__float2bfloat16_rn(va.x - __bfloat162float(h0)),
                                __float2bfloat16_rn(va.y - __bfloat162float(h1)));
            __nv_bfloat162 alo1(__float2bfloat16_rn(va.z - __bfloat162float(h2)),
                                __float2bfloat16_rn(va.w - __bfloat162float(h3)));
            ((uint32_t*)(sAhi + row * SR + o * 8))[0] = *(uint32_t*)&ahi0;
            ((uint32_t*)(sAhi + row * SR + o * 8))[1] = *(uint32_t*)&ahi1;
            ((uint32_t*)(sAlo + row * SR + o * 8))[0] = *(uint32_t*)&alo0;
            ((uint32_t*)(sAlo + row * SR + o * 8))[1] = *(uint32_t*)&alo1;
            __nv_bfloat16 g0 = __float2bfloat16_rn(vb.x), g1 = __float2bfloat16_rn(vb.y);
            __nv_bfloat16 g2 = __float2bfloat16_rn(vb.z), g3 = __float2bfloat16_rn(vb.w);
            __nv_bfloat162 bhi0(g0, g1), bhi1(g2, g3);
            __nv_bfloat162 blo0(__float2bfloat16_rn(vb.x - __bfloat162float(g0)),
                                __float2bfloat16_rn(vb.y - __bfloat162float(g1)));
            __nv_bfloat162 blo1(__float2bfloat16_rn(vb.z - __bfloat162float(g2)),
                                __float2bfloat16_rn(vb.w - __bfloat162float(g3)));
            ((uint32_t*)(sBhi + row * SR + o * 8))[0] = *(uint32_t*)&bhi0;
            ((uint32_t*)(sBhi + row * SR + o * 8))[1] = *(uint32_t*)&bhi1;
            ((uint32_t*)(sBlo + row * SR + o * 8))[0] = *(uint32_t*)&blo0;
            ((uint32_t*)(sBlo + row * SR + o * 8))[1] = *(uint32_t*)&blo1;
        }
        __syncthreads();
        #pragma unroll
        for (int kk = 0; kk < 4; kk++) {
            uint32_t ah[4], al[4];
            ldsm4(ah[0], ah[1], ah[2], ah[3], uAhi + aOff + kk * 32);
            ldsm4(al[0], al[1], al[2], al[3], uAlo + aOff + kk * 32);
            #pragma unroll
            for (int j = 0; j < 8; j++) {
                uint32_t h0, h1, h2, h3, l0, l1, l2, l3;
                ldsm4(h0, h1, h2, h3, uBhi + bOff + j * 16 * SR + kk * 32);
                ldsm4(l0, l1, l2, l3, uBlo + bOff + j * 16 * SR + kk * 32);
                mma16816(acc[2 * j],     ah, h0, h1);
                mma16816(acc[2 * j + 1], ah, h2, h3);
                mma16816(acc[2 * j],     ah, l0, l1);
                mma16816(acc[2 * j + 1], ah, l2, l3);
                mma16816(acc[2 * j],     al, h0, h1);
                mma16816(acc[2 * j + 1], al, h2, h3);
            }
        }
    }

    float* out = g_gram_part + (size_t)blockIdx.x * NPIX;
    int g = lane >> 2, tt = lane & 3;
    #pragma unroll
    for (int i = 0; i < 16; i++) {
        int col = i * 8 + tt * 2;
        int r0 = ws * 16 + g;
        *(float2*)&out[r0 * 128 + col]       = make_float2(acc[i][0], acc[i][1]);
        *(float2*)&out[(r0 + 8) * 128 + col] = make_float2(acc[i][2], acc[i][3]);
    }
}

// ---------------------------------------------------------------------------
// dist reduce: 128 partials -> 8 -> Dist.
// ---------------------------------------------------------------------------
__global__ __launch_bounds__(128)
void dist_partial_kernel() {  // grid (128, 8)
    int e = blockIdx.x * 128 + threadIdx.x;
    int y = blockIdx.y;
    float s = 0.f;
    #pragma unroll
    for (int pp = 0; pp < 16; pp++)
        s += g_gram_part[(size_t)(y * 16 + pp) * NPIX + e];
    g_dtmp[(size_t)y * NPIX + e] = s;
}

__global__ __launch_bounds__(128)
void dist_final_kernel() {  // grid 128
    int bi = blockIdx.x, t = threadIdx.x;
    int e = bi * 128 + t;
    float s = 0.f;
    #pragma unroll
    for (int y = 0; y < 8; y++) s += g_dtmp[(size_t)y * NPIX + e];
    float n1 = g_np1[bi * 4] + g_np1[bi * 4 + 1] + g_np1[bi * 4 + 2] + g_np1[bi * 4 + 3];
    float n2 = g_np2[t * 4] + g_np2[t * 4 + 1] + g_np2[t * 4 + 2] + g_np2[t * 4 + 3];
    float d2 = n1 + n2 - 2.f * s;
    g_dist[e] = sqrtf(fmaxf(d2, 0.f));
}

// ---------------------------------------------------------------------------
// final: CE over Dist rows + psd scalar (128+128 scalar sums).
// c is warp-uniform -> lane 0 stores, NO lane reduction (R5 bug).
// ---------------------------------------------------------------------------
__global__ __launch_bounds__(1024)
void final_kernel(float* __restrict__ out) {
    __shared__ float sbufC[32];
    int t = threadIdx.x, lane = t & 31, warp = t >> 5;

    float c = 0.f;
    #pragma unroll
    for (int rr = 0; rr < 4; rr++) {
        int row = warp * 4 + rr;
        const float* rp = g_dist + row * 128;
        float e0 = rp[lane], e1 = rp[lane + 32], e2 = rp[lane + 64], e3 = rp[lane + 96];
        float m = fmaxf(fmaxf(e0, e1), fmaxf(e2, e3));
        #pragma unroll
        for (int o = 16; o; o >>= 1) m = fmaxf(m, __shfl_xor_sync(0xffffffffu, m, o));
        float se = expf(e0 - m) + expf(e1 - m) + expf(e2 - m) + expf(e3 - m);
        #pragma unroll
        for (int o = 16; o; o >>= 1) se += __shfl_xor_sync(0xffffffffu, se, o);
        c += rp[row] - (m + logf(se));  // warp-uniform
    }
    if (lane == 0) sbufC[warp] = c;
    __syncthreads();
    if (t == 0) {
        float cs = 0.f;
        #pragma unroll
        for (int w = 0; w < 32; w++) cs += sbufC[w];
        float ce = -cs / 128.f;
        float lsum = 0.f, asum = 0.f;
        #pragma unroll
        for (int k = 0; k < 128; k++) { lsum += g_redL[k]; asum += g_redA[k]; }
        float r = lsum / 16384.f - logf(asum / 16384.f);
        out[0] = ce - 0.1f * r;
    }
}

// ---------------------------------------------------------------------------
extern "C" void kernel_launch(void* const* d_in, const int* in_sizes, int n_in,
                              void* d_out, int out_size) {
    const float* x1 = (const float*)d_in[0];
    const float* x2 = (const float*)d_in[1];
    float* out = (float*)d_out;

    const int SMEM_GRAM = 4 * 128 * SR;  // 73,728 B

    static cudaStream_t s1 = 0;
    static cudaEvent_t ev_fork, ev_row, ev_join;
    static bool inited = false;
    if (!inited) {
        cudaStreamCreateWithFlags(&s1, cudaStreamNonBlocking);
        cudaEventCreateWithFlags(&ev_fork, cudaEventDisableTiming);
        cudaEventCreateWithFlags(&ev_row, cudaEventDisableTiming);
        cudaEventCreateWithFlags(&ev_join, cudaEventDisableTiming);
        cudaFuncSetAttribute(gram_fused_kernel,
                             cudaFuncAttributeMaxDynamicSharedMemorySize, SMEM_GRAM);
        inited = true;
    }

    cudaEventRecord(ev_fork, 0);
    cudaStreamWaitEvent(s1, ev_fork, 0);

    // FFT / psd chain (legacy)
    fft_row_kernel<<<512, 256>>>(x1, x2);
    cudaEventRecord(ev_row, 0);  // norm partials + g_spec ready
    fft_col_kernel<<<256, 256>>>();
    psd_red_kernel<<<128, 128>>>();

    // Gram chain (s1)
    gram_fused_kernel<<<128, 256, SMEM_GRAM, s1>>>(x1, x2);
    dist_partial_kernel<<<dim3(128, 8), 128, 0, s1>>>();
    cudaStreamWaitEvent(s1, ev_row, 0);
    dist_final_kernel<<<128, 128, 0, s1>>>();
    cudaEventRecord(ev_join, s1);

    cudaStreamWaitEvent(0, ev_join, 0);
    final_kernel<<<1, 1024>>>(out);
}

// round 15
// speedup vs baseline: 1.1993x; 1.1993x over previous
#include <cuda_runtime.h>
#include <cuda_bf16.h>
#include <cuda_fp16.h>
#include <math.h>
#include <stdint.h>

// OneClassLoss on GB300 — R8.
//  legacy: fft_row (512 blk, half2 spec + norms) -> fft_col (256 blk, psd
//          accumulated over 8 pairs -> 16 partials) -> psd_red (128 blk)
//  s1:     gram_fused (64 blk, K=256, cp.async double-buffered fp32 staging,
//          bf16 hi/lo 3-term HMMA) -> dist_partial -> [ev_row] dist_final
//  join:   final (CE + lane-parallel psd scalar sums)
// Lesson R14: wall-clock ~= sum of work across both streams; keep gram at 64
// blocks (same SM footprint) and hide its DRAM latency internally.

#define NPIX 16384

__device__ __half2 g_spec[128 * NPIX];      // row-FFT out (8 MB)
__device__ float  g_psd_part[16 * NPIX];    // psd partials (1 MB)
__device__ float  g_gram_part[64 * NPIX];   // partial Gram per K-chunk (4 MB)
__device__ float  g_dtmp[4 * NPIX];
__device__ float  g_np1[512], g_np2[512];   // norm partials (4 per image)
__device__ float  g_dist[NPIX];
__device__ float  g_redL[128], g_redA[128]; // per-col psd reduced scalars

// ---------------------------------------------------------------------------
// 128-pt DIF radix-2 complex FFT, one warp, 4 values/lane (n = r*32+lane).
// Output slot p holds bin rev7(p).
// ---------------------------------------------------------------------------
__device__ __forceinline__ void fft128(float vr[4], float vi[4],
                                       const float2* __restrict__ tw, int lane) {
    #pragma unroll
    for (int r = 0; r < 2; r++) {  // h=64
        float2 w = tw[r * 32 + lane];
        float ur = vr[r], ui = vi[r], xr = vr[r + 2], xi = vi[r + 2];
        vr[r] = ur + xr; vi[r] = ui + xi;
        float dr = ur - xr, di = ui - xi;
        vr[r + 2] = dr * w.x - di * w.y;
        vi[r + 2] = dr * w.y + di * w.x;
    }
    {  // h=32
        float2 w = tw[2 * lane];
        #pragma unroll
        for (int half = 0; half < 2; half++) {
            int r = half * 2;
            float ur = vr[r], ui = vi[r], xr = vr[r + 1], xi = vi[r + 1];
            vr[r] = ur + xr; vi[r] = ui + xi;
            float dr = ur - xr, di = ui - xi;
            vr[r + 1] = dr * w.x - di * w.y;
            vi[r + 1] = dr * w.y + di * w.x;
        }
    }
    #pragma unroll
    for (int st = 0; st < 5; st++) {  // h = 16,8,4,2,1
        const int h = 16 >> st;
        const int k = (lane & (h - 1)) * (64 / h);
        float2 w = tw[k];
        bool hiLane = (lane & h) != 0;
        #pragma unroll
        for (int r = 0; r < 4; r++) {
            float ar = vr[r], ai = vi[r];
            float br = __shfl_xor_sync(0xffffffffu, ar, h);
            float bi = __shfl_xor_sync(0xffffffffu, ai, h);
            if (hiLane) {
                float dr = br - ar, di = bi - ai;
                vr[r] = dr * w.x - di * w.y;
                vi[r] = dr * w.y + di * w.x;
            } else {
                vr[r] = ar + br;
                vi[r] = ai + bi;
            }
        }
    }
}

__device__ __forceinline__ void init_tw(float2* s_tw, int t) {
    if (t < 64) {
        float sn, cs;
        sincosf(-6.283185307179586f * (float)t / 128.0f, &sn, &cs);
        s_tw[t] = make_float2(cs, sn);
    }
}

// ---------------------------------------------------------------------------
// fft_row: grid 512 = 128 pairs x 4 row-groups. z = x1 + i*x2; de-bitrev +
// transpose in smem; half2 g_spec[pair][col][rows]; norm partials.
// ---------------------------------------------------------------------------
__global__ __launch_bounds__(256)
void fft_row_kernel(const float* __restrict__ x1, const float* __restrict__ x2) {
    __shared__ float s_re[128 * 33], s_im[128 * 33];
    __shared__ float2 s_tw[64];
    __shared__ float s_red[16];

    int t = threadIdx.x, lane = t & 31, warp = t >> 5;  // 8 warps
    int b = blockIdx.x >> 2, rg = blockIdx.x & 3;
    const float* p1 = x1 + (size_t)b * NPIX;
    const float* p2 = x2 + (size_t)b * NPIX;

    init_tw(s_tw, t);
    __syncthreads();

    float n1 = 0.f, n2 = 0.f;
    #pragma unroll
    for (int q = 0; q < 4; q++) {
        int rl = warp * 4 + q;
        int row = rg * 32 + rl;
        float vr[4], vi[4];
        #pragma unroll
        for (int r = 0; r < 4; r++) {
            float xr = p1[row * 128 + r * 32 + lane];
            float xi = p2[row * 128 + r * 32 + lane];
            vr[r] = xr; vi[r] = xi;
            n1 += xr * xr; n2 += xi * xi;
        }
        fft128(vr, vi, s_tw, lane);
        #pragma unroll
        for (int r = 0; r < 4; r++) {
            int p = r * 32 + lane;
            int k = __brev((unsigned)p) >> 25;  // natural col bin
            s_re[k * 33 + rl] = vr[r];
            s_im[k * 33 + rl] = vi[r];
        }
    }

    #pragma unroll
    for (int o = 16; o; o >>= 1) {
        n1 += __shfl_xor_sync(0xffffffffu, n1, o);
        n2 += __shfl_xor_sync(0xffffffffu, n2, o);
    }
    if (lane == 0) { s_red[warp] = n1; s_red[8 + warp] = n2; }
    __syncthreads();
    if (t == 0) {
        float a = 0.f, c = 0.f;
        #pragma unroll
        for (int w = 0; w < 8; w++) { a += s_red[w]; c += s_red[8 + w]; }
        g_np1[blockIdx.x] = a; g_np2[blockIdx.x] = c;
    }

    __half2* spec = g_spec + (size_t)b * NPIX;
    #pragma unroll
    for (int it = 0; it < 16; it++) {
        int c = warp + it * 8;
        spec[c * 128 + rg * 32 + lane] =
            __floats2half2_rn(s_re[c * 33 + lane], s_im[c * 33 + lane]);
    }
}

// ---------------------------------------------------------------------------
// fft_col: grid 256 = 16 pair-groups x 16 col-groups; accumulate |Z|^2 over
// 8 pairs in regs -> g_psd_part[pg].
// ---------------------------------------------------------------------------
__global__ __launch_bounds__(256)
void fft_col_kernel() {
    __shared__ float2 s_tw[64];
    int t = threadIdx.x, lane = t & 31, warp = t >> 5;
    int pg = blockIdx.x >> 4, cg = blockIdx.x & 15;
    int col = cg * 8 + warp;
    init_tw(s_tw, t);
    __syncthreads();

    float acc[4] = {0.f, 0.f, 0.f, 0.f};
    #pragma unroll 2
    for (int q = 0; q < 8; q++) {
        int b = pg * 8 + q;
        const __half2* spec = g_spec + (size_t)b * NPIX + col * 128;
        float vr[4], vi[4];
        #pragma unroll
        for (int r = 0; r < 4; r++) {
            float2 z = __half22float2(spec[r * 32 + lane]);
            vr[r] = z.x; vi[r] = z.y;
        }
        fft128(vr, vi, s_tw, lane);
        #pragma unroll
        for (int r = 0; r < 4; r++)
            acc[r] += vr[r] * vr[r] + vi[r] * vi[r];
    }
    float* outp = g_psd_part + (size_t)pg * NPIX + col * 128;
    #pragma unroll
    for (int r = 0; r < 4; r++) outp[r * 32 + lane] = acc[r];
}

// ---------------------------------------------------------------------------
// psd_red: grid 128. Sum 16 partials for slot + Hermitian partner; block-
// reduce log(avg)/avg -> g_redL/g_redA[col].
// ---------------------------------------------------------------------------
__global__ __launch_bounds__(128)
void psd_red_kernel() {
    __shared__ float sbuf[8];
    int t = threadIdx.x, lane = t & 31, warp = t >> 5;
    int col = blockIdx.x, p = t;
    int i = col * 128 + p;
    int kr = __brev((unsigned)p) >> 25;
    int pp = __brev((unsigned)((128 - kr) & 127)) >> 25;
    int ip = ((128 - col) & 127) * 128 + pp;
    float Ti = 0.f, Tp = 0.f;
    #pragma unroll
    for (int y = 0; y < 16; y++) {
        Ti += g_psd_part[(size_t)y * NPIX + i];
        Tp += g_psd_part[(size_t)y * NPIX + ip];
    }
    float avg = (Ti + Tp) * (0.5f / 256.f);
    float v1 = logf(avg), v2 = avg;
    #pragma unroll
    for (int o = 16; o; o >>= 1) {
        v1 += __shfl_xor_sync(0xffffffffu, v1, o);
        v2 += __shfl_xor_sync(0xffffffffu, v2, o);
    }
    if (lane == 0) { sbuf[warp] = v1; sbuf[4 + warp] = v2; }
    __syncthreads();
    if (t == 0) {
        g_redL[col] = sbuf[0] + sbuf[1] + sbuf[2] + sbuf[3];
        g_redA[col] = sbuf[4] + sbuf[5] + sbuf[6] + sbuf[7];
    }
}

// ---------------------------------------------------------------------------
// gram_fused: 64 blocks, K=256 (4 stages of 64). cp.async double-buffered
// fp32 staging hides DRAM latency behind convert+mma of previous stage.
// ---------------------------------------------------------------------------
__device__ __forceinline__ void ldsm4(uint32_t& r0, uint32_t& r1,
                                      uint32_t& r2, uint32_t& r3, uint32_t a) {
    asm volatile("ldmatrix.sync.aligned.m8n8.x4.shared.b16 {%0,%1,%2,%3}, [%4];"
                 : "=r"(r0), "=r"(r1), "=r"(r2), "=r"(r3) : "r"(a));
}
__device__ __forceinline__ void mma16816(float d[4], const uint32_t a[4],
                                         uint32_t b0, uint32_t b1) {
    asm volatile(
        "mma.sync.aligned.m16n8k16.row.col.f32.bf16.bf16.f32 "
        "{%0,%1,%2,%3}, {%4,%5,%6,%7}, {%8,%9}, {%0,%1,%2,%3};"
        : "+f"(d[0]), "+f"(d[1]), "+f"(d[2]), "+f"(d[3])
        : "r"(a[0]), "r"(a[1]), "r"(a[2]), "r"(a[3]), "r"(b0), "r"(b1));
}
__device__ __forceinline__ void cpasync16(uint32_t dst, const void* src) {
    asm volatile("cp.async.cg.shared.global [%0], [%1], 16;"
                 :: "r"(dst), "l"(src));
}

#define SR 144                      // bf16 smem row stride (64 bf16 + pad)
#define F32BUF 65536                // one fp32 staging buffer (A 32K + B 32K)
#define SMEM_GRAM (2 * F32BUF + 4 * 128 * SR)  // 131072 + 73728 = 204800 B

__global__ __launch_bounds__(256, 1)
void gram_fused_kernel(const float* __restrict__ x1, const float* __restrict__ x2) {
    extern __shared__ char gsm[];
    char* sF   = gsm;                       // 2 x (A32K + B32K) fp32 staging
    char* sAhi = gsm + 2 * F32BUF;
    char* sAlo = sAhi + 128 * SR;
    char* sBhi = sAhi + 2 * 128 * SR;
    char* sBlo = sAhi + 3 * 128 * SR;
    uint32_t uF   = (uint32_t)__cvta_generic_to_shared(sF);
    uint32_t uAhi = (uint32_t)__cvta_generic_to_shared(sAhi);
    uint32_t uAlo = (uint32_t)__cvta_generic_to_shared(sAlo);
    uint32_t uBhi = (uint32_t)__cvta_generic_to_shared(sBhi);
    uint32_t uBlo = (uint32_t)__cvta_generic_to_shared(sBlo);

    int t = threadIdx.x, lane = t & 31, ws = t >> 5;
    int k0 = blockIdx.x * 256;

    float acc[16][4];
    #pragma unroll
    for (int i = 0; i < 16; i++)
        #pragma unroll
        for (int j = 0; j < 4; j++) acc[i][j] = 0.f;

    uint32_t aOff = (ws * 16 + (lane & 15)) * SR + (lane >> 4) * 16;
    uint32_t bOff = ((lane & 7) + ((lane >> 4) << 3)) * SR + ((lane & 8) << 1);

    // issue stage 0 loads
    {
        uint32_t fb = uF;
        #pragma unroll
        for (int c = 0; c < 8; c++) {
            int id = t + c * 256;
            int row = id >> 4, o = id & 15;
            cpasync16(fb + row * 256 + o * 16,
                      x1 + (size_t)row * NPIX + k0 + o * 4);
            cpasync16(fb + 32768 + row * 256 + o * 16,
                      x2 + (size_t)row * NPIX + k0 + o * 4);
        }
        asm volatile("cp.async.commit_group;");
    }

    for (int stg = 0; stg < 4; stg++) {
        int d = stg & 1;
        asm volatile("cp.async.wait_group 0;");
        __syncthreads();  // staged fp32 visible; previous mma done (bf16 free)

        // convert fp32 staging -> bf16 hi/lo smem
        char* fbA = sF + d * F32BUF;
        char* fbB = fbA + 32768;
        #pragma unroll
        for (int c = 0; c < 8; c++) {
            int id = t + c * 256;
            int row = id >> 4, o = id & 15;
            float4 va = *(const float4*)(fbA + row * 256 + o * 16);
            float4 vb = *(const float4*)(fbB + row * 256 + o * 16);
            __nv_bfloat16 h0 = __float2bfloat16_rn(va.x), h1 = __float2bfloat16_rn(va.y);
            __nv_bfloat16 h2 = __float2bfloat16_rn(va.z), h3 = __float2bfloat16_rn(va.w);
            __nv_bfloat162 ahi0(h0, h1), ahi1(h2, h3);
            __nv_bfloat162 alo0(__float2bfloat16_rn(va.x - __bfloat162float(h0)),
                                __float2bfloat16_rn(va.y - __bfloat162float(h1)));
            __nv_bfloat162 alo1(__float2bfloat16_rn(va.z - __bfloat162float(h2)),
                                __float2bfloat16_rn(va.w - __bfloat162float(h3)));
            ((uint32_t*)(sAhi + row * SR + o * 8))[0] = *(uint32_t*)&ahi0;
            ((uint32_t*)(sAhi + row * SR + o * 8))[1] = *(uint32_t*)&ahi1;
            ((uint32_t*)(sAlo + row * SR + o * 8))[0] = *(uint32_t*)&alo0;
            ((uint32_t*)(sAlo + row * SR + o * 8))[1] = *(uint32_t*)&alo1;
            __nv_bfloat16 g0 = __float2bfloat16_rn(vb.x), g1 = __float2bfloat16_rn(vb.y);
            __nv_bfloat16 g2 = __float2bfloat16_rn(vb.z), g3 = __float2bfloat16_rn(vb.w);
            __nv_bfloat162 bhi0(g0, g1), bhi1(g2, g3);
            __nv_bfloat162 blo0(__float2bfloat16_rn(vb.x - __bfloat162float(g0)),
                                __float2bfloat16_rn(vb.y - __bfloat162float(g1)));
            __nv_bfloat162 blo1(__float2bfloat16_rn(vb.z - __bfloat162float(g2)),
                                __float2bfloat16_rn(vb.w - __bfloat162float(g3)));
            ((uint32_t*)(sBhi + row * SR + o * 8))[0] = *(uint32_t*)&bhi0;
            ((uint32_t*)(sBhi + row * SR + o * 8))[1] = *(uint32_t*)&bhi1;
            ((uint32_t*)(sBlo + row * SR + o * 8))[0] = *(uint32_t*)&blo0;
            ((uint32_t*)(sBlo + row * SR + o * 8))[1] = *(uint32_t*)&blo1;
        }

        // issue next stage's loads (overlap with this stage's mma)
        if (stg < 3) {
            int ks = k0 + (stg + 1) * 64;
            uint32_t fb = uF + (1 - d) * F32BUF;
            #pragma unroll
            for (int c = 0; c < 8; c++) {
                int id = t + c * 256;
                int row = id >> 4, o = id & 15;
                cpasync16(fb + row * 256 + o * 16,
                          x1 + (size_t)row * NPIX + ks + o * 4);
                cpasync16(fb + 32768 + row * 256 + o * 16,
                          x2 + (size_t)row * NPIX + ks + o * 4);
            }
            asm volatile("cp.async.commit_group;");
        }
        __syncthreads();  // bf16 tiles ready

        #pragma unroll
        for (int kk = 0; kk < 4; kk++) {
            uint32_t ah[4], al[4];
            ldsm4(ah[0], ah[1], ah[2], ah[3], uAhi + aOff + kk * 32);
            ldsm4(al[0], al[1], al[2], al[3], uAlo + aOff + kk * 32);
            #pragma unroll
            for (int j = 0; j < 8; j++) {
                uint32_t h0, h1, h2, h3, l0, l1, l2, l3;
                ldsm4(h0, h1, h2, h3, uBhi + bOff + j * 16 * SR + kk * 32);
                ldsm4(l0, l1, l2, l3, uBlo + bOff + j * 16 * SR + kk * 32);
                mma16816(acc[2 * j],     ah, h0, h1);
                mma16816(acc[2 * j + 1], ah, h2, h3);
                mma16816(acc[2 * j],     ah, l0, l1);
                mma16816(acc[2 * j + 1], ah, l2, l3);
                mma16816(acc[2 * j],     al, h0, h1);
                mma16816(acc[2 * j + 1], al, h2, h3);
            }
        }
    }

    float* out = g_gram_part + (size_t)blockIdx.x * NPIX;
    int g = lane >> 2, tt = lane & 3;
    #pragma unroll
    for (int i = 0; i < 16; i++) {
        int col = i * 8 + tt * 2;
        int r0 = ws * 16 + g;
        *(float2*)&out[r0 * 128 + col]       = make_float2(acc[i][0], acc[i][1]);
        *(float2*)&out[(r0 + 8) * 128 + col] = make_float2(acc[i][2], acc[i][3]);
    }
}

// ---------------------------------------------------------------------------
// dist reduce: 64 partials -> 4 -> Dist.
// ---------------------------------------------------------------------------
__global__ __launch_bounds__(128)
void dist_partial_kernel() {  // grid (128, 4)
    int e = blockIdx.x * 128 + threadIdx.x;
    int y = blockIdx.y;
    float s = 0.f;
    #pragma unroll
    for (int pp = 0; pp < 16; pp++)
        s += g_gram_part[(size_t)(y * 16 + pp) * NPIX + e];
    g_dtmp[(size_t)y * NPIX + e] = s;
}

__global__ __launch_bounds__(128)
void dist_final_kernel() {  // grid 128
    int bi = blockIdx.x, t = threadIdx.x;
    int e = bi * 128 + t;
    float s = g_dtmp[e] + g_dtmp[NPIX + e] + g_dtmp[2 * NPIX + e] + g_dtmp[3 * NPIX + e];
    float n1 = g_np1[bi * 4] + g_np1[bi * 4 + 1] + g_np1[bi * 4 + 2] + g_np1[bi * 4 + 3];
    float n2 = g_np2[t * 4] + g_np2[t * 4 + 1] + g_np2[t * 4 + 2] + g_np2[t * 4 + 3];
    float d2 = n1 + n2 - 2.f * s;
    g_dist[e] = sqrtf(fmaxf(d2, 0.f));
}

// ---------------------------------------------------------------------------
// final: CE over Dist rows + lane-parallel psd scalar sums.
// c is warp-uniform -> lane 0 stores, NO lane reduction.
// ---------------------------------------------------------------------------
__global__ __launch_bounds__(1024)
void final_kernel(float* __restrict__ out) {
    __shared__ float sbufC[32], sb2[16];
    int t = threadIdx.x, lane = t & 31, warp = t >> 5;

    float c = 0.f;
    #pragma unroll
    for (int rr = 0; rr < 4; rr++) {
        int row = warp * 4 + rr;
        const float* rp = g_dist + row * 128;
        float e0 = rp[lane], e1 = rp[lane + 32], e2 = rp[lane + 64], e3 = rp[lane + 96];
        float m = fmaxf(fmaxf(e0, e1), fmaxf(e2, e3));
        #pragma unroll
        for (int o = 16; o; o >>= 1) m = fmaxf(m, __shfl_xor_sync(0xffffffffu, m, o));
        float se = expf(e0 - m) + expf(e1 - m) + expf(e2 - m) + expf(e3 - m);
        #pragma unroll
        for (int o = 16; o; o >>= 1) se += __shfl_xor_sync(0xffffffffu, se, o);
        c += rp[row] - (m + logf(se));  // warp-uniform
    }
    if (lane == 0) sbufC[warp] = c;

    // psd scalar sums: warps 0..3 cover t = 0..127
    float l = 0.f, a = 0.f;
    if (t < 128) { l = g_redL[t]; a = g_redA[t]; }
    #pragma unroll
    for (int o = 16; o; o >>= 1) {
        l += __shfl_xor_sync(0xffffffffu, l, o);
        a += __shfl_xor_sync(0xffffffffu, a, o);
    }
    if (warp < 4 && lane == 0) { sb2[warp] = l; sb2[8 + warp] = a; }
    __syncthreads();
    if (t == 0) {
        float cs = 0.f;
        #pragma unroll
        for (int w = 0; w < 32; w++) cs += sbufC[w];
        float ce = -cs / 128.f;
        float lsum = sb2[0] + sb2[1] + sb2[2] + sb2[3];
        float asum = sb2[8] + sb2[9] + sb2[10] + sb2[11];
        float r = lsum / 16384.f - logf(asum / 16384.f);
        out[0] = ce - 0.1f * r;
    }
}

// ---------------------------------------------------------------------------
extern "C" void kernel_launch(void* const* d_in, const int* in_sizes, int n_in,
                              void* d_out, int out_size) {
    const float* x1 = (const float*)d_in[0];
    const float* x2 = (const float*)d_in[1];
    float* out = (float*)d_out;

    static cudaStream_t s1 = 0;
    static cudaEvent_t ev_fork, ev_row, ev_join;
    static bool inited = false;
    if (!inited) {
        cudaStreamCreateWithFlags(&s1, cudaStreamNonBlocking);
        cudaEventCreateWithFlags(&ev_fork, cudaEventDisableTiming);
        cudaEventCreateWithFlags(&ev_row, cudaEventDisableTiming);
        cudaEventCreateWithFlags(&ev_join, cudaEventDisableTiming);
        cudaFuncSetAttribute(gram_fused_kernel,
                             cudaFuncAttributeMaxDynamicSharedMemorySize, SMEM_GRAM);
        inited = true;
    }

    cudaEventRecord(ev_fork, 0);
    cudaStreamWaitEvent(s1, ev_fork, 0);

    // FFT / psd chain (legacy)
    fft_row_kernel<<<512, 256>>>(x1, x2);
    cudaEventRecord(ev_row, 0);  // norm partials + g_spec ready
    fft_col_kernel<<<256, 256>>>();
    psd_red_kernel<<<128, 128>>>();

    // Gram chain (s1)
    gram_fused_kernel<<<64, 256, SMEM_GRAM, s1>>>(x1, x2);
    dist_partial_kernel<<<dim3(128, 4), 128, 0, s1>>>();
    cudaStreamWaitEvent(s1, ev_row, 0);
    dist_final_kernel<<<128, 128, 0, s1>>>();
    cudaEventRecord(ev_join, s1);

    cudaStreamWaitEvent(0, ev_join, 0);
    final_kernel<<<1, 1024>>>(out);
}